// round 7
// baseline (speedup 1.0000x reference)
#include <cuda_runtime.h>
#include <cuda_fp16.h>
#include <math.h>

#define NB   8
#define NC   256
#define NH   128
#define NW   128
#define NHW  16384
#define NMID 64
#define NANG 4
#define NPT  512
#define WEPS 1e-5f

// ---------------- scratch (static __device__, no allocations) ----------------
__device__ __half g_xh[(size_t)NB * NHW * NC];     // 67 MB  x in NHWC fp16
__device__ float g_trig[2 * NANG];
__device__ float g_A[NANG * NHW];
__device__ float g_mpart[(size_t)NANG * NB * NC * NPT];
__device__ float g_ca[NANG * NB * NC];
__device__ float g_avg[(size_t)NANG * NB * NHW];
__device__ float g_maxm[(size_t)NANG * NB * NHW];
__device__ float g_sa[(size_t)NANG * NB * NHW];

// ---------------- helpers ----------------
__device__ __forceinline__ float ncoord(int j) { return -1.0f + (float)j * (2.0f / 127.0f); }
__device__ __forceinline__ float sigm(float v) { return 1.0f / (1.0f + expf(-v)); }

// Accumulate w * 8 fp16 channels into acc[8].
__device__ __forceinline__ void acc_row8(float* acc, float w, const uint4 h) {
    const __half2* hp = (const __half2*)&h;
#pragma unroll
    for (int i = 0; i < 4; i++) {
        float2 f = __half22float2(hp[i]);
        acc[2 * i]     = fmaf(w, f.x, acc[2 * i]);
        acc[2 * i + 1] = fmaf(w, f.y, acc[2 * i + 1]);
    }
}
// Accumulate w * 4 fp16 channels into acc[4].
__device__ __forceinline__ void acc_row4(float* acc, float w, const uint2 h) {
    const __half2* hp = (const __half2*)&h;
#pragma unroll
    for (int i = 0; i < 2; i++) {
        float2 f = __half22float2(hp[i]);
        acc[2 * i]     = fmaf(w, f.x, acc[2 * i]);
        acc[2 * i + 1] = fmaf(w, f.y, acc[2 * i + 1]);
    }
}

// Bilinear gather into 8 fp32 channel accumulators (channels lane*8..lane*8+7).
__device__ __forceinline__ void gather8(int b, float fix, float fiy, int lane, float* acc) {
#pragma unroll
    for (int i = 0; i < 8; i++) acc[i] = 0.f;
    float fx0 = floorf(fix), fy0 = floorf(fiy);
    float wx1 = fix - fx0, wx0 = 1.0f - wx1;
    float wy1 = fiy - fy0, wy0 = 1.0f - wy1;
    float cx[4] = {fx0, fx0 + 1.0f, fx0,        fx0 + 1.0f};
    float cy[4] = {fy0, fy0,        fy0 + 1.0f, fy0 + 1.0f};
    float cw[4] = {wx0 * wy0, wx1 * wy0, wx0 * wy1, wx1 * wy1};
#pragma unroll
    for (int k = 0; k < 4; k++) {
        float fx = cx[k], fy = cy[k], wv = cw[k];
        if (fx >= 0.f && fx <= 127.f && fy >= 0.f && fy <= 127.f && wv > WEPS) {
            const uint4* row = (const uint4*)(g_xh +
                ((size_t)b * NHW + (int)fy * NW + (int)fx) * NC);
            acc_row8(acc, wv, row[lane]);
        }
    }
}

// ---------------- kernels ----------------

// A map (with per-thread trig; block 0 publishes g_trig for later kernels).
__global__ void k_Amap(const float* __restrict__ angles) {
    int id = blockIdx.x * 256 + threadIdx.x;
    int a = id >> 14, src = id & (NHW - 1);
    float ang = angles[a];
    float c_ = cosf(ang), s_ = sinf(ang);
    if (blockIdx.x == 0 && threadIdx.x < NANG) {
        float aa = angles[threadIdx.x];
        g_trig[2 * threadIdx.x]     = cosf(aa);
        g_trig[2 * threadIdx.x + 1] = sinf(aa);
    }
    int sy = src >> 7, sx = src & 127;
    float dx = (float)sx - 63.5f, dy = (float)sy - 63.5f;
    float pxf = c_ * dx + s_ * dy + 63.5f;
    float pyf = -s_ * dx + c_ * dy + 63.5f;
    int px0 = (int)floorf(pxf + 0.5f) - 2;
    int py0 = (int)floorf(pyf + 0.5f) - 2;
    float acc = 0.f;
    for (int py = py0; py < py0 + 5; py++) {
        for (int px = px0; px < px0 + 5; px++) {
            if ((unsigned)px < 128u && (unsigned)py < 128u) {
                float X = ncoord(px), Y = ncoord(py);
                float gx = c_ * X - s_ * Y, gy = s_ * X + c_ * Y;
                float ix = (gx + 1.0f) * 63.5f, iy = (gy + 1.0f) * 63.5f;
                float tx = 1.0f - fabsf(ix - (float)sx);
                float ty = 1.0f - fabsf(iy - (float)sy);
                if (tx > 0.f && ty > 0.f) acc += tx * ty;
            }
        }
    }
    g_A[id] = acc * (1.0f / (float)NHW);
}

// NCHW -> NHWC(fp16) transpose (64-channel tiles, half2 stores) fused with
// per-angle weighted-mean partials (fp32).
__global__ void k_transpose_mean(const float* __restrict__ x) {
    __shared__ float s[64][33];
    int b = blockIdx.z, c0 = blockIdx.y * 64, p0 = blockIdx.x * 32;
    int tx = threadIdx.x, ty = threadIdx.y;
    float v0 = x[((size_t)(b * NC + c0 + ty)) * NHW + p0 + tx];
    float v1 = x[((size_t)(b * NC + c0 + 32 + ty)) * NHW + p0 + tx];
    s[ty][tx] = v0;
    s[ty + 32][tx] = v1;
#pragma unroll
    for (int a = 0; a < NANG; a++) {
        float Aw = g_A[a * NHW + p0 + tx];
        float r0 = v0 * Aw, r1 = v1 * Aw;
#pragma unroll
        for (int o = 16; o; o >>= 1) {
            r0 += __shfl_xor_sync(0xffffffffu, r0, o);
            r1 += __shfl_xor_sync(0xffffffffu, r1, o);
        }
        if (tx == 0) {
            size_t base = ((size_t)((a * NB + b) * NC + c0 + ty)) * NPT + blockIdx.x;
            g_mpart[base] = r0;
            g_mpart[base + (size_t)32 * NPT] = r1;
        }
    }
    __syncthreads();
    __half2 h2 = __floats2half2_rn(s[2 * tx][ty], s[2 * tx + 1][ty]);
    *(__half2*)(g_xh + ((size_t)b * NHW + p0 + ty) * NC + c0 + 2 * tx) = h2;
}

// Mean reduction (512 partials/channel) + channel attention MLP, one block per (a,b).
__global__ void k_chatt(const float* __restrict__ w1, const float* __restrict__ bng,
                        const float* __restrict__ bnb, const float* __restrict__ bnm,
                        const float* __restrict__ bnv, const float* __restrict__ w2) {
    __shared__ float sm[NC];
    __shared__ float sh[NMID];
    int ab = blockIdx.x;
    int tid = threadIdx.x;
    {
        const float4* src = (const float4*)(g_mpart + (size_t)(ab * NC + tid) * NPT);
        float ssum = 0.f;
#pragma unroll 4
        for (int i = 0; i < NPT / 4; i++) {
            float4 v = src[i];
            ssum += (v.x + v.y) + (v.z + v.w);
        }
        sm[tid] = ssum;
    }
    __syncthreads();
    if (tid < NMID) {
        float hv = 0.f;
        const float* w1r = w1 + tid * NC;
        for (int c = 0; c < NC; c++) hv = fmaf(sm[c], w1r[c], hv);
        hv = (hv - bnm[tid]) * rsqrtf(bnv[tid] + 1e-5f) * bng[tid] + bnb[tid];
        sh[tid] = fmaxf(hv, 0.f);
    }
    __syncthreads();
    float cv = 0.f;
    const float* w2r = w2 + tid * NMID;
    for (int j = 0; j < NMID; j++) cv = fmaf(sh[j], w2r[j], cv);
    g_ca[ab * NC + tid] = sigm(cv);
}

// Channel-attended rotated stats; 2 adjacent pixels per warp (MLP 8).
__global__ void k_avgmax() {
    int w2 = blockIdx.x * 8 + (threadIdx.x >> 5);
    int lane = threadIdx.x & 31;
    int a = w2 >> 16;
    int b = (w2 >> 13) & 7;
    int p = (w2 & 8191) * 2;
    float c_ = g_trig[2 * a], s_ = g_trig[2 * a + 1];
    float X0 = ncoord(p & 127), X1 = ncoord((p & 127) + 1), Y = ncoord(p >> 7);
    float acc0[8], acc1[8];
    {
        float gx = c_ * X0 - s_ * Y, gy = s_ * X0 + c_ * Y;
        gather8(b, (gx + 1.0f) * 63.5f, (gy + 1.0f) * 63.5f, lane, acc0);
    }
    {
        float gx = c_ * X1 - s_ * Y, gy = s_ * X1 + c_ * Y;
        gather8(b, (gx + 1.0f) * 63.5f, (gy + 1.0f) * 63.5f, lane, acc1);
    }
    const float4* car = (const float4*)(g_ca + (size_t)(a * NB + b) * NC);
    float4 ca0 = car[lane * 2], ca1 = car[lane * 2 + 1];
    float cav[8] = {ca0.x, ca0.y, ca0.z, ca0.w, ca1.x, ca1.y, ca1.z, ca1.w};
    float sum0 = 0.f, mx0 = -1e30f, sum1 = 0.f, mx1 = -1e30f;
#pragma unroll
    for (int i = 0; i < 8; i++) {
        float u = cav[i] * acc0[i], v = cav[i] * acc1[i];
        sum0 += u; mx0 = fmaxf(mx0, u);
        sum1 += v; mx1 = fmaxf(mx1, v);
    }
#pragma unroll
    for (int o = 16; o; o >>= 1) {
        sum0 += __shfl_xor_sync(0xffffffffu, sum0, o);
        mx0 = fmaxf(mx0, __shfl_xor_sync(0xffffffffu, mx0, o));
        sum1 += __shfl_xor_sync(0xffffffffu, sum1, o);
        mx1 = fmaxf(mx1, __shfl_xor_sync(0xffffffffu, mx1, o));
    }
    if (lane == 0) {
        size_t base = (size_t)(a * NB + b) * NHW + p;
        g_avg[base]     = sum0 * (1.0f / (float)NC);
        g_avg[base + 1] = sum1 * (1.0f / (float)NC);
        g_maxm[base]     = mx0;
        g_maxm[base + 1] = mx1;
    }
}

__global__ void k_conv(const float* __restrict__ wsp) {
    __shared__ float sw[98];
    int tid = threadIdx.x;
    if (tid < 98) sw[tid] = wsp[tid];
    __syncthreads();
    int id = blockIdx.x * 256 + tid;
    int ab = id >> 14;
    int p = id & (NHW - 1);
    int py = p >> 7, px = p & 127;
    const float* av = g_avg + (size_t)ab * NHW;
    const float* mxp = g_maxm + (size_t)ab * NHW;
    float acc = 0.f;
#pragma unroll
    for (int ky = 0; ky < 7; ky++) {
        int yy = py + ky - 3;
        if ((unsigned)yy < 128u) {
#pragma unroll
            for (int kx = 0; kx < 7; kx++) {
                int xx = px + kx - 3;
                if ((unsigned)xx < 128u) {
                    int q = yy * NW + xx;
                    acc = fmaf(sw[ky * 7 + kx], av[q], acc);
                    acc = fmaf(sw[49 + ky * 7 + kx], mxp[q], acc);
                }
            }
        }
    }
    g_sa[id] = sigm(acc);
}

// Fused inverse pass, composed-gather dedup, 2 WARPS PER PIXEL (channel halves).
// Block = 512 threads = 16 warps = 8 pixels; each warp gathers 128 channels
// (uint2/lane). Twice the warps per pixel -> twice the loads in flight per
// SMSP for the same wavefront total. __launch_bounds__(512,2) -> 2 blocks/SM.
__global__ void __launch_bounds__(512, 2) k_fused(float* __restrict__ out) {
    __shared__ float s[8][260];
    int b = blockIdx.x >> 11;            // 2048 8-pixel tiles per image
    int q0 = (blockIdx.x & 2047) * 8;
    int wid = threadIdx.x >> 5, lane = threadIdx.x & 31;
    int pixl = wid >> 1, half = wid & 1;
    int q = q0 + pixl;
    float X = ncoord(q & 127), Y = ncoord(q >> 7);
    float res[4] = {0.f, 0.f, 0.f, 0.f};

#pragma unroll
    for (int a = 0; a < NANG; a++) {
        float c_ = g_trig[2 * a], s_ = g_trig[2 * a + 1];
        float gx = c_ * X + s_ * Y, gy = -s_ * X + c_ * Y;   // inverse grid
        float ixv = (gx + 1.0f) * 63.5f, iyv = (gy + 1.0f) * 63.5f;
        float x0 = floorf(ixv), y0 = floorf(iyv);
        float wx1 = ixv - x0, wx0 = 1.0f - wx1;
        float wy1 = iyv - y0, wy0 = 1.0f - wy1;

        // pass 1: bounding corner of forward-mapped inverse corners
        float minfx = 1e9f, minfy = 1e9f;
#pragma unroll
        for (int j = 0; j < 4; j++) {
            float fpx = x0 + (float)(j & 1);
            float fpy = y0 + (float)(j >> 1);
            float wi = ((j & 1) ? wx1 : wx0) * ((j >> 1) ? wy1 : wy0);
            if (fpx >= 0.f && fpx <= 127.f && fpy >= 0.f && fpy <= 127.f && wi > WEPS) {
                float Xp = ncoord((int)fpx), Yp = ncoord((int)fpy);
                float fgx = c_ * Xp - s_ * Yp, fgy = s_ * Xp + c_ * Yp;
                minfx = fminf(minfx, (fgx + 1.0f) * 63.5f);
                minfy = fminf(minfy, (fgy + 1.0f) * 63.5f);
            }
        }
        if (minfx < 500.f) {
            int bx = (int)floorf(minfx), by = (int)floorf(minfy);
            float cellx = (float)(bx + (lane & 3));
            float celly = (float)(by + ((lane >> 2) & 3));
            // pass 2: this lane's cell weight (lanes 0..15 meaningful)
            float wc = 0.f;
#pragma unroll
            for (int j = 0; j < 4; j++) {
                float fpx = x0 + (float)(j & 1);
                float fpy = y0 + (float)(j >> 1);
                float wi = ((j & 1) ? wx1 : wx0) * ((j >> 1) ? wy1 : wy0);
                if (fpx >= 0.f && fpx <= 127.f && fpy >= 0.f && fpy <= 127.f && wi > WEPS) {
                    int ip = (int)fpy * NW + (int)fpx;
                    float sav = g_sa[(size_t)(a * NB + b) * NHW + ip];
                    float Xp = ncoord((int)fpx), Yp = ncoord((int)fpy);
                    float fgx = c_ * Xp - s_ * Yp, fgy = s_ * Xp + c_ * Yp;
                    float tx = fmaxf(0.f, 1.0f - fabsf((fgx + 1.0f) * 63.5f - cellx));
                    float ty = fmaxf(0.f, 1.0f - fabsf((fgy + 1.0f) * 63.5f - celly));
                    wc = fmaf(wi * sav, tx * ty, wc);
                }
            }
            float t[4] = {0.f, 0.f, 0.f, 0.f};
#pragma unroll
            for (int k = 0; k < 16; k++) {
                float w = __shfl_sync(0xffffffffu, wc, k);
                int cxk = bx + (k & 3), cyk = by + (k >> 2);
                if (w > WEPS && (unsigned)cxk < 128u && (unsigned)cyk < 128u) {
                    const uint2* row = (const uint2*)(g_xh +
                        ((size_t)b * NHW + cyk * NW + cxk) * NC + half * 128);
                    acc_row4(t, w, row[lane]);
                }
            }
            const float4* car = (const float4*)(g_ca + (size_t)(a * NB + b) * NC);
            float4 ca0 = car[half * 32 + lane];
            res[0] = fmaf(ca0.x, t[0], res[0]); res[1] = fmaf(ca0.y, t[1], res[1]);
            res[2] = fmaf(ca0.z, t[2], res[2]); res[3] = fmaf(ca0.w, t[3], res[3]);
        }
    }

    // smem transpose: s[pixel][channel] -> NCHW stores with /4 folded in
    *(float4*)&s[pixl][half * 128 + lane * 4] = make_float4(res[0], res[1], res[2], res[3]);
    __syncthreads();
    int pix = lane & 7, grp = lane >> 3;    // 4 groups x 8 pixels
#pragma unroll
    for (int it = 0; it < 4; it++) {
        int c = wid * 16 + grp * 4 + it;
        float v = s[pix][c];
        out[((size_t)(b * NC + c)) * NHW + q0 + pix] = v * 0.25f;
    }
}

// ---------------- launch ----------------
extern "C" void kernel_launch(void* const* d_in, const int* in_sizes, int n_in,
                              void* d_out, int out_size) {
    const float* x      = (const float*)d_in[0];
    const float* angles = (const float*)d_in[1];
    const float* w1     = (const float*)d_in[2];
    const float* bng    = (const float*)d_in[3];
    const float* bnb    = (const float*)d_in[4];
    const float* bnm    = (const float*)d_in[5];
    const float* bnv    = (const float*)d_in[6];
    const float* w2     = (const float*)d_in[7];
    const float* wsp    = (const float*)d_in[8];
    float* out = (float*)d_out;

    dim3 tb(32, 32);
    k_Amap<<<(NANG * NHW) / 256, 256>>>(angles);
    k_transpose_mean<<<dim3(NPT, NC / 64, NB), tb>>>(x);
    k_chatt<<<NANG * NB, 256>>>(w1, bng, bnb, bnm, bnv, w2);
    k_avgmax<<<(NANG * NB * NHW / 2) / 8, 256>>>();
    k_conv<<<(NANG * NB * NHW) / 256, 256>>>(wsp);
    k_fused<<<NB * NHW / 8, 512>>>(out);
}

// round 8
// speedup vs baseline: 1.2316x; 1.2316x over previous
#include <cuda_runtime.h>
#include <cuda_fp16.h>
#include <math.h>

#define NB   8
#define NC   256
#define NH   128
#define NW   128
#define NHW  16384
#define NMID 64
#define NANG 4
#define NPT  512
#define WEPS 1e-5f

// ---------------- scratch (static __device__, no allocations) ----------------
__device__ __half g_xh[(size_t)NB * NHW * NC];     // 67 MB  x in NHWC fp16
__device__ float g_trig[2 * NANG];
__device__ float g_A[NANG * NHW];
__device__ float g_mpart[(size_t)NANG * NB * NC * NPT];
__device__ float g_ca[NANG * NB * NC];
__device__ float g_avg[(size_t)NANG * NB * NHW];
__device__ float g_maxm[(size_t)NANG * NB * NHW];
__device__ float g_sa[(size_t)NANG * NB * NHW];

// ---------------- helpers ----------------
__device__ __forceinline__ float ncoord(int j) { return -1.0f + (float)j * (2.0f / 127.0f); }
__device__ __forceinline__ float ncoordf(float j) { return -1.0f + j * (2.0f / 127.0f); }
__device__ __forceinline__ float sigm(float v) { return 1.0f / (1.0f + expf(-v)); }

// Accumulate wh * 8 fp16 channels into 4 half2 accumulators (4 HFMA2).
__device__ __forceinline__ void hacc_row8(__half2* t, __half2 wh, const uint4 h) {
    const __half2* hp = (const __half2*)&h;
#pragma unroll
    for (int i = 0; i < 4; i++) t[i] = __hfma2(wh, hp[i], t[i]);
}

// Bilinear gather into 4 half2 accumulators (channels lane*8..lane*8+7).
__device__ __forceinline__ void gather8h(const __half* xb, float fix, float fiy,
                                         int lane, __half2* acc) {
#pragma unroll
    for (int i = 0; i < 4; i++) acc[i] = __half2half2(__ushort_as_half(0));
    float fx0 = floorf(fix), fy0 = floorf(fiy);
    float wx1 = fix - fx0, wx0 = 1.0f - wx1;
    float wy1 = fiy - fy0, wy0 = 1.0f - wy1;
    float cx[4] = {fx0, fx0 + 1.0f, fx0,        fx0 + 1.0f};
    float cy[4] = {fy0, fy0,        fy0 + 1.0f, fy0 + 1.0f};
    float cw[4] = {wx0 * wy0, wx1 * wy0, wx0 * wy1, wx1 * wy1};
#pragma unroll
    for (int k = 0; k < 4; k++) {
        float fx = cx[k], fy = cy[k], wv = cw[k];
        if (fx >= 0.f && fx <= 127.f && fy >= 0.f && fy <= 127.f && wv > WEPS) {
            const uint4* row = (const uint4*)(xb + ((int)fy * NW + (int)fx) * NC);
            hacc_row8(acc, __float2half2_rn(wv), row[lane]);
        }
    }
}

// ---------------- kernels ----------------

// A map (with per-thread trig; block 0 publishes g_trig for later kernels).
__global__ void k_Amap(const float* __restrict__ angles) {
    int id = blockIdx.x * 256 + threadIdx.x;
    int a = id >> 14, src = id & (NHW - 1);
    float ang = angles[a];
    float c_ = cosf(ang), s_ = sinf(ang);
    if (blockIdx.x == 0 && threadIdx.x < NANG) {
        float aa = angles[threadIdx.x];
        g_trig[2 * threadIdx.x]     = cosf(aa);
        g_trig[2 * threadIdx.x + 1] = sinf(aa);
    }
    int sy = src >> 7, sx = src & 127;
    float dx = (float)sx - 63.5f, dy = (float)sy - 63.5f;
    float pxf = c_ * dx + s_ * dy + 63.5f;
    float pyf = -s_ * dx + c_ * dy + 63.5f;
    int px0 = (int)floorf(pxf + 0.5f) - 2;
    int py0 = (int)floorf(pyf + 0.5f) - 2;
    float acc = 0.f;
    for (int py = py0; py < py0 + 5; py++) {
        for (int px = px0; px < px0 + 5; px++) {
            if ((unsigned)px < 128u && (unsigned)py < 128u) {
                float X = ncoord(px), Y = ncoord(py);
                float gx = c_ * X - s_ * Y, gy = s_ * X + c_ * Y;
                float ix = (gx + 1.0f) * 63.5f, iy = (gy + 1.0f) * 63.5f;
                float tx = 1.0f - fabsf(ix - (float)sx);
                float ty = 1.0f - fabsf(iy - (float)sy);
                if (tx > 0.f && ty > 0.f) acc += tx * ty;
            }
        }
    }
    g_A[id] = acc * (1.0f / (float)NHW);
}

// NCHW -> NHWC(fp16) transpose (64-channel tiles, half2 stores) fused with
// per-angle weighted-mean partials (fp32).
__global__ void k_transpose_mean(const float* __restrict__ x) {
    __shared__ float s[64][33];
    int b = blockIdx.z, c0 = blockIdx.y * 64, p0 = blockIdx.x * 32;
    int tx = threadIdx.x, ty = threadIdx.y;
    float v0 = x[((size_t)(b * NC + c0 + ty)) * NHW + p0 + tx];
    float v1 = x[((size_t)(b * NC + c0 + 32 + ty)) * NHW + p0 + tx];
    s[ty][tx] = v0;
    s[ty + 32][tx] = v1;
#pragma unroll
    for (int a = 0; a < NANG; a++) {
        float Aw = g_A[a * NHW + p0 + tx];
        float r0 = v0 * Aw, r1 = v1 * Aw;
#pragma unroll
        for (int o = 16; o; o >>= 1) {
            r0 += __shfl_xor_sync(0xffffffffu, r0, o);
            r1 += __shfl_xor_sync(0xffffffffu, r1, o);
        }
        if (tx == 0) {
            size_t base = ((size_t)((a * NB + b) * NC + c0 + ty)) * NPT + blockIdx.x;
            g_mpart[base] = r0;
            g_mpart[base + (size_t)32 * NPT] = r1;
        }
    }
    __syncthreads();
    __half2 h2 = __floats2half2_rn(s[2 * tx][ty], s[2 * tx + 1][ty]);
    *(__half2*)(g_xh + ((size_t)b * NHW + p0 + ty) * NC + c0 + 2 * tx) = h2;
}

// Mean reduction (512 partials/channel) + channel attention MLP, one block per (a,b).
__global__ void k_chatt(const float* __restrict__ w1, const float* __restrict__ bng,
                        const float* __restrict__ bnb, const float* __restrict__ bnm,
                        const float* __restrict__ bnv, const float* __restrict__ w2) {
    __shared__ float sm[NC];
    __shared__ float sh[NMID];
    int ab = blockIdx.x;
    int tid = threadIdx.x;
    {
        const float4* src = (const float4*)(g_mpart + (size_t)(ab * NC + tid) * NPT);
        float ssum = 0.f;
#pragma unroll 4
        for (int i = 0; i < NPT / 4; i++) {
            float4 v = src[i];
            ssum += (v.x + v.y) + (v.z + v.w);
        }
        sm[tid] = ssum;
    }
    __syncthreads();
    if (tid < NMID) {
        float hv = 0.f;
        const float* w1r = w1 + tid * NC;
        for (int c = 0; c < NC; c++) hv = fmaf(sm[c], w1r[c], hv);
        hv = (hv - bnm[tid]) * rsqrtf(bnv[tid] + 1e-5f) * bng[tid] + bnb[tid];
        sh[tid] = fmaxf(hv, 0.f);
    }
    __syncthreads();
    float cv = 0.f;
    const float* w2r = w2 + tid * NMID;
    for (int j = 0; j < NMID; j++) cv = fmaf(sh[j], w2r[j], cv);
    g_ca[ab * NC + tid] = sigm(cv);
}

// Channel-attended rotated stats; 2 adjacent pixels per warp, fp16 HFMA2 gather.
__global__ void k_avgmax() {
    int w2 = blockIdx.x * 8 + (threadIdx.x >> 5);
    int lane = threadIdx.x & 31;
    int a = w2 >> 16;
    int b = (w2 >> 13) & 7;
    int p = (w2 & 8191) * 2;
    float c_ = g_trig[2 * a], s_ = g_trig[2 * a + 1];
    const __half* xb = g_xh + (size_t)b * NHW * NC;
    float X0 = ncoord(p & 127), X1 = ncoord((p & 127) + 1), Y = ncoord(p >> 7);
    __half2 acc0[4], acc1[4];
    {
        float gx = c_ * X0 - s_ * Y, gy = s_ * X0 + c_ * Y;
        gather8h(xb, (gx + 1.0f) * 63.5f, (gy + 1.0f) * 63.5f, lane, acc0);
    }
    {
        float gx = c_ * X1 - s_ * Y, gy = s_ * X1 + c_ * Y;
        gather8h(xb, (gx + 1.0f) * 63.5f, (gy + 1.0f) * 63.5f, lane, acc1);
    }
    const float4* car = (const float4*)(g_ca + (size_t)(a * NB + b) * NC);
    float4 ca0 = car[lane * 2], ca1 = car[lane * 2 + 1];
    float cav[8] = {ca0.x, ca0.y, ca0.z, ca0.w, ca1.x, ca1.y, ca1.z, ca1.w};
    float sum0 = 0.f, mx0 = -1e30f, sum1 = 0.f, mx1 = -1e30f;
#pragma unroll
    for (int i = 0; i < 4; i++) {
        float2 f0 = __half22float2(acc0[i]);
        float2 f1 = __half22float2(acc1[i]);
        float u0 = cav[2 * i] * f0.x, u1 = cav[2 * i + 1] * f0.y;
        float v0 = cav[2 * i] * f1.x, v1 = cav[2 * i + 1] * f1.y;
        sum0 += u0 + u1; mx0 = fmaxf(mx0, fmaxf(u0, u1));
        sum1 += v0 + v1; mx1 = fmaxf(mx1, fmaxf(v0, v1));
    }
#pragma unroll
    for (int o = 16; o; o >>= 1) {
        sum0 += __shfl_xor_sync(0xffffffffu, sum0, o);
        mx0 = fmaxf(mx0, __shfl_xor_sync(0xffffffffu, mx0, o));
        sum1 += __shfl_xor_sync(0xffffffffu, sum1, o);
        mx1 = fmaxf(mx1, __shfl_xor_sync(0xffffffffu, mx1, o));
    }
    if (lane == 0) {
        size_t base = (size_t)(a * NB + b) * NHW + p;
        g_avg[base]     = sum0 * (1.0f / (float)NC);
        g_avg[base + 1] = sum1 * (1.0f / (float)NC);
        g_maxm[base]     = mx0;
        g_maxm[base + 1] = mx1;
    }
}

__global__ void k_conv(const float* __restrict__ wsp) {
    __shared__ float sw[98];
    int tid = threadIdx.x;
    if (tid < 98) sw[tid] = wsp[tid];
    __syncthreads();
    int id = blockIdx.x * 256 + tid;
    int ab = id >> 14;
    int p = id & (NHW - 1);
    int py = p >> 7, px = p & 127;
    const float* av = g_avg + (size_t)ab * NHW;
    const float* mxp = g_maxm + (size_t)ab * NHW;
    float acc = 0.f;
#pragma unroll
    for (int ky = 0; ky < 7; ky++) {
        int yy = py + ky - 3;
        if ((unsigned)yy < 128u) {
#pragma unroll
            for (int kx = 0; kx < 7; kx++) {
                int xx = px + kx - 3;
                if ((unsigned)xx < 128u) {
                    int q = yy * NW + xx;
                    acc = fmaf(sw[ky * 7 + kx], av[q], acc);
                    acc = fmaf(sw[49 + ky * 7 + kx], mxp[q], acc);
                }
            }
        }
    }
    g_sa[id] = sigm(acc);
}

// Fused inverse pass: 1 warp / pixel (16 warps = 16 consecutive pixels).
// Issue-count optimized: separable min for the 4x4 cell-window anchor,
// ballot-mask loop over ONLY active cells, fp16 HFMA2 tile accumulation
// (per-angle tile t, fp32 res accumulation with ca).
__global__ void __launch_bounds__(512, 2) k_fused(float* __restrict__ out) {
    __shared__ float s[16][260];
    int b = blockIdx.x >> 10;            // 1024 16-pixel tiles per image
    int q0 = (blockIdx.x & 1023) * 16;
    int wid = threadIdx.x >> 5, lane = threadIdx.x & 31;
    int q = q0 + wid;
    float X = ncoord(q & 127), Y = ncoord(q >> 7);
    const __half* xb = g_xh + (size_t)b * NHW * NC;
    float res[8];
#pragma unroll
    for (int i = 0; i < 8; i++) res[i] = 0.f;

#pragma unroll
    for (int a = 0; a < NANG; a++) {
        float c_ = g_trig[2 * a], s_ = g_trig[2 * a + 1];
        const float* saab = g_sa + (size_t)(a * NB + b) * NHW;
        float gx = c_ * X + s_ * Y, gy = -s_ * X + c_ * Y;   // inverse grid
        float ixv = (gx + 1.0f) * 63.5f, iyv = (gy + 1.0f) * 63.5f;
        float x0 = floorf(ixv), y0 = floorf(iyv);
        float wx1 = ixv - x0, wx0 = 1.0f - wx1;
        float wy1 = iyv - y0, wy0 = 1.0f - wy1;

        // separable min of forward-mapped corners (unrestricted; slack covers
        // invalid corners -- their cells produce wc=0 and drop out of the mask)
        float Xp0 = ncoordf(x0), Xp1 = Xp0 + (2.0f / 127.0f);
        float Yp0 = ncoordf(y0), Yp1 = Yp0 + (2.0f / 127.0f);
        float minfgx = fminf(c_ * Xp0, c_ * Xp1) + fminf(-s_ * Yp0, -s_ * Yp1);
        float minfgy = fminf(s_ * Xp0, s_ * Xp1) + fminf(c_ * Yp0, c_ * Yp1);
        int bx = (int)floorf((minfgx + 1.0f) * 63.5f);
        int by = (int)floorf((minfgy + 1.0f) * 63.5f);

        // this lane's cell weight (lanes 0..15 meaningful)
        float cellx = (float)(bx + (lane & 3));
        float celly = (float)(by + ((lane >> 2) & 3));
        float wc = 0.f;
#pragma unroll
        for (int j = 0; j < 4; j++) {
            float fpx = x0 + (float)(j & 1);
            float fpy = y0 + (float)(j >> 1);
            float wi = ((j & 1) ? wx1 : wx0) * ((j >> 1) ? wy1 : wy0);
            if (fpx >= 0.f && fpx <= 127.f && fpy >= 0.f && fpy <= 127.f && wi > WEPS) {
                float sav = saab[(int)fpy * NW + (int)fpx];
                float fgx = c_ * ncoordf(fpx) - s_ * ncoordf(fpy);
                float fgy = s_ * ncoordf(fpx) + c_ * ncoordf(fpy);
                float tx = fmaxf(0.f, 1.0f - fabsf((fgx + 1.0f) * 63.5f - cellx));
                float ty = fmaxf(0.f, 1.0f - fabsf((fgy + 1.0f) * 63.5f - celly));
                wc = fmaf(wi * sav, tx * ty, wc);
            }
        }

        unsigned mask = __ballot_sync(0xffffffffu, wc > WEPS) & 0xffffu;
        __half2 t[4];
#pragma unroll
        for (int i = 0; i < 4; i++) t[i] = __half2half2(__ushort_as_half(0));
        while (mask) {
            int k = __ffs(mask) - 1;
            mask &= mask - 1;
            float w = __shfl_sync(0xffffffffu, wc, k);
            int cxk = bx + (k & 3), cyk = by + (k >> 2);
            if ((unsigned)cxk < 128u && (unsigned)cyk < 128u) {
                const uint4* row = (const uint4*)(xb + (cyk * NW + cxk) * NC);
                hacc_row8(t, __float2half2_rn(w), row[lane]);
            }
        }

        const float4* car = (const float4*)(g_ca + (size_t)(a * NB + b) * NC);
        float4 ca0 = car[lane * 2], ca1 = car[lane * 2 + 1];
        float2 f0 = __half22float2(t[0]), f1 = __half22float2(t[1]);
        float2 f2 = __half22float2(t[2]), f3 = __half22float2(t[3]);
        res[0] = fmaf(ca0.x, f0.x, res[0]); res[1] = fmaf(ca0.y, f0.y, res[1]);
        res[2] = fmaf(ca0.z, f1.x, res[2]); res[3] = fmaf(ca0.w, f1.y, res[3]);
        res[4] = fmaf(ca1.x, f2.x, res[4]); res[5] = fmaf(ca1.y, f2.y, res[5]);
        res[6] = fmaf(ca1.z, f3.x, res[6]); res[7] = fmaf(ca1.w, f3.y, res[7]);
    }

    // smem transpose: s[pixel][channel] -> NCHW stores with /4 folded in
    *(float4*)&s[wid][lane * 8]     = make_float4(res[0], res[1], res[2], res[3]);
    *(float4*)&s[wid][lane * 8 + 4] = make_float4(res[4], res[5], res[6], res[7]);
    __syncthreads();
    int pix = lane & 15, hl = lane >> 4;
#pragma unroll
    for (int it = 0; it < 8; it++) {
        int c = wid * 16 + hl * 8 + it;
        float v = s[pix][c];
        out[((size_t)(b * NC + c)) * NHW + q0 + pix] = v * 0.25f;
    }
}

// ---------------- launch ----------------
extern "C" void kernel_launch(void* const* d_in, const int* in_sizes, int n_in,
                              void* d_out, int out_size) {
    const float* x      = (const float*)d_in[0];
    const float* angles = (const float*)d_in[1];
    const float* w1     = (const float*)d_in[2];
    const float* bng    = (const float*)d_in[3];
    const float* bnb    = (const float*)d_in[4];
    const float* bnm    = (const float*)d_in[5];
    const float* bnv    = (const float*)d_in[6];
    const float* w2     = (const float*)d_in[7];
    const float* wsp    = (const float*)d_in[8];
    float* out = (float*)d_out;

    dim3 tb(32, 32);
    k_Amap<<<(NANG * NHW) / 256, 256>>>(angles);
    k_transpose_mean<<<dim3(NPT, NC / 64, NB), tb>>>(x);
    k_chatt<<<NANG * NB, 256>>>(w1, bng, bnb, bnm, bnv, w2);
    k_avgmax<<<(NANG * NB * NHW / 2) / 8, 256>>>();
    k_conv<<<(NANG * NB * NHW) / 256, 256>>>(wsp);
    k_fused<<<NB * NHW / 16, 512>>>(out);
}

// round 9
// speedup vs baseline: 1.8399x; 1.4939x over previous
#include <cuda_runtime.h>
#include <cuda_fp16.h>
#include <math.h>

#define NB   8
#define NC   256
#define NH   128
#define NW   128
#define NHW  16384
#define NMID 64
#define NANG 4
#define NPT  512
#define WEPS 1e-5f

// ---------------- scratch (static __device__, no allocations) ----------------
__device__ __half g_xh[(size_t)NB * NHW * NC];     // 67 MB  x in NHWC fp16
__device__ float g_trig[2 * NANG];
__device__ float g_A[NANG * NHW];
__device__ float g_mpart[(size_t)NANG * NB * NC * NPT];
__device__ float g_ca[NANG * NB * NC];
__device__ float g_avg[(size_t)NANG * NB * NHW];
__device__ float g_maxm[(size_t)NANG * NB * NHW];
__device__ float g_sa[(size_t)NANG * NB * NHW];

// ---------------- helpers ----------------
__device__ __forceinline__ float ncoord(int j) { return -1.0f + (float)j * (2.0f / 127.0f); }
__device__ __forceinline__ float ncoordf(float j) { return -1.0f + j * (2.0f / 127.0f); }
__device__ __forceinline__ float sigm(float v) { return 1.0f / (1.0f + expf(-v)); }

// Accumulate w * 8 fp16 channels (one uint4 row chunk) into fp32 acc[8].
__device__ __forceinline__ void acc_row8(float* acc, float w, const uint4 h) {
    const __half2* hp = (const __half2*)&h;
#pragma unroll
    for (int i = 0; i < 4; i++) {
        float2 f = __half22float2(hp[i]);
        acc[2 * i]     = fmaf(w, f.x, acc[2 * i]);
        acc[2 * i + 1] = fmaf(w, f.y, acc[2 * i + 1]);
    }
}

// Bilinear gather into 8 fp32 channel accumulators (channels lane*8..lane*8+7).
__device__ __forceinline__ void gather8(const __half* xb, float fix, float fiy,
                                        int lane, float* acc) {
#pragma unroll
    for (int i = 0; i < 8; i++) acc[i] = 0.f;
    float fx0 = floorf(fix), fy0 = floorf(fiy);
    float wx1 = fix - fx0, wx0 = 1.0f - wx1;
    float wy1 = fiy - fy0, wy0 = 1.0f - wy1;
    float cx[4] = {fx0, fx0 + 1.0f, fx0,        fx0 + 1.0f};
    float cy[4] = {fy0, fy0,        fy0 + 1.0f, fy0 + 1.0f};
    float cw[4] = {wx0 * wy0, wx1 * wy0, wx0 * wy1, wx1 * wy1};
#pragma unroll
    for (int k = 0; k < 4; k++) {
        float fx = cx[k], fy = cy[k], wv = cw[k];
        if (fx >= 0.f && fx <= 127.f && fy >= 0.f && fy <= 127.f && wv > WEPS) {
            const uint4* row = (const uint4*)(xb + ((int)fy * NW + (int)fx) * NC);
            acc_row8(acc, wv, row[lane]);
        }
    }
}

// ---------------- kernels ----------------

// A map (with per-thread trig; block 0 publishes g_trig for later kernels).
__global__ void k_Amap(const float* __restrict__ angles) {
    int id = blockIdx.x * 256 + threadIdx.x;
    int a = id >> 14, src = id & (NHW - 1);
    float ang = angles[a];
    float c_ = cosf(ang), s_ = sinf(ang);
    if (blockIdx.x == 0 && threadIdx.x < NANG) {
        float aa = angles[threadIdx.x];
        g_trig[2 * threadIdx.x]     = cosf(aa);
        g_trig[2 * threadIdx.x + 1] = sinf(aa);
    }
    int sy = src >> 7, sx = src & 127;
    float dx = (float)sx - 63.5f, dy = (float)sy - 63.5f;
    float pxf = c_ * dx + s_ * dy + 63.5f;
    float pyf = -s_ * dx + c_ * dy + 63.5f;
    int px0 = (int)floorf(pxf + 0.5f) - 2;
    int py0 = (int)floorf(pyf + 0.5f) - 2;
    float acc = 0.f;
    for (int py = py0; py < py0 + 5; py++) {
        for (int px = px0; px < px0 + 5; px++) {
            if ((unsigned)px < 128u && (unsigned)py < 128u) {
                float X = ncoord(px), Y = ncoord(py);
                float gx = c_ * X - s_ * Y, gy = s_ * X + c_ * Y;
                float ix = (gx + 1.0f) * 63.5f, iy = (gy + 1.0f) * 63.5f;
                float tx = 1.0f - fabsf(ix - (float)sx);
                float ty = 1.0f - fabsf(iy - (float)sy);
                if (tx > 0.f && ty > 0.f) acc += tx * ty;
            }
        }
    }
    g_A[id] = acc * (1.0f / (float)NHW);
}

// NCHW -> NHWC(fp16) transpose (64-channel tiles, half2 stores) fused with
// per-angle weighted-mean partials (fp32).
__global__ void k_transpose_mean(const float* __restrict__ x) {
    __shared__ float s[64][33];
    int b = blockIdx.z, c0 = blockIdx.y * 64, p0 = blockIdx.x * 32;
    int tx = threadIdx.x, ty = threadIdx.y;
    float v0 = x[((size_t)(b * NC + c0 + ty)) * NHW + p0 + tx];
    float v1 = x[((size_t)(b * NC + c0 + 32 + ty)) * NHW + p0 + tx];
    s[ty][tx] = v0;
    s[ty + 32][tx] = v1;
#pragma unroll
    for (int a = 0; a < NANG; a++) {
        float Aw = g_A[a * NHW + p0 + tx];
        float r0 = v0 * Aw, r1 = v1 * Aw;
#pragma unroll
        for (int o = 16; o; o >>= 1) {
            r0 += __shfl_xor_sync(0xffffffffu, r0, o);
            r1 += __shfl_xor_sync(0xffffffffu, r1, o);
        }
        if (tx == 0) {
            size_t base = ((size_t)((a * NB + b) * NC + c0 + ty)) * NPT + blockIdx.x;
            g_mpart[base] = r0;
            g_mpart[base + (size_t)32 * NPT] = r1;
        }
    }
    __syncthreads();
    __half2 h2 = __floats2half2_rn(s[2 * tx][ty], s[2 * tx + 1][ty]);
    *(__half2*)(g_xh + ((size_t)b * NHW + p0 + ty) * NC + c0 + 2 * tx) = h2;
}

// Mean reduction (512 partials/channel) + channel attention MLP, one block per (a,b).
__global__ void k_chatt(const float* __restrict__ w1, const float* __restrict__ bng,
                        const float* __restrict__ bnb, const float* __restrict__ bnm,
                        const float* __restrict__ bnv, const float* __restrict__ w2) {
    __shared__ float sm[NC];
    __shared__ float sh[NMID];
    int ab = blockIdx.x;
    int tid = threadIdx.x;
    {
        const float4* src = (const float4*)(g_mpart + (size_t)(ab * NC + tid) * NPT);
        float ssum = 0.f;
#pragma unroll 4
        for (int i = 0; i < NPT / 4; i++) {
            float4 v = src[i];
            ssum += (v.x + v.y) + (v.z + v.w);
        }
        sm[tid] = ssum;
    }
    __syncthreads();
    if (tid < NMID) {
        float hv = 0.f;
        const float* w1r = w1 + tid * NC;
        for (int c = 0; c < NC; c++) hv = fmaf(sm[c], w1r[c], hv);
        hv = (hv - bnm[tid]) * rsqrtf(bnv[tid] + 1e-5f) * bng[tid] + bnb[tid];
        sh[tid] = fmaxf(hv, 0.f);
    }
    __syncthreads();
    float cv = 0.f;
    const float* w2r = w2 + tid * NMID;
    for (int j = 0; j < NMID; j++) cv = fmaf(sh[j], w2r[j], cv);
    g_ca[ab * NC + tid] = sigm(cv);
}

// Channel-attended rotated stats; 2 adjacent pixels per warp (fp32 FFMA gather).
__global__ void k_avgmax() {
    int w2 = blockIdx.x * 8 + (threadIdx.x >> 5);
    int lane = threadIdx.x & 31;
    int a = w2 >> 16;
    int b = (w2 >> 13) & 7;
    int p = (w2 & 8191) * 2;
    float c_ = g_trig[2 * a], s_ = g_trig[2 * a + 1];
    const __half* xb = g_xh + (size_t)b * NHW * NC;
    float X0 = ncoord(p & 127), X1 = ncoord((p & 127) + 1), Y = ncoord(p >> 7);
    float acc0[8], acc1[8];
    {
        float gx = c_ * X0 - s_ * Y, gy = s_ * X0 + c_ * Y;
        gather8(xb, (gx + 1.0f) * 63.5f, (gy + 1.0f) * 63.5f, lane, acc0);
    }
    {
        float gx = c_ * X1 - s_ * Y, gy = s_ * X1 + c_ * Y;
        gather8(xb, (gx + 1.0f) * 63.5f, (gy + 1.0f) * 63.5f, lane, acc1);
    }
    const float4* car = (const float4*)(g_ca + (size_t)(a * NB + b) * NC);
    float4 ca0 = car[lane * 2], ca1 = car[lane * 2 + 1];
    float cav[8] = {ca0.x, ca0.y, ca0.z, ca0.w, ca1.x, ca1.y, ca1.z, ca1.w};
    float sum0 = 0.f, mx0 = -1e30f, sum1 = 0.f, mx1 = -1e30f;
#pragma unroll
    for (int i = 0; i < 8; i++) {
        float u = cav[i] * acc0[i], v = cav[i] * acc1[i];
        sum0 += u; mx0 = fmaxf(mx0, u);
        sum1 += v; mx1 = fmaxf(mx1, v);
    }
#pragma unroll
    for (int o = 16; o; o >>= 1) {
        sum0 += __shfl_xor_sync(0xffffffffu, sum0, o);
        mx0 = fmaxf(mx0, __shfl_xor_sync(0xffffffffu, mx0, o));
        sum1 += __shfl_xor_sync(0xffffffffu, sum1, o);
        mx1 = fmaxf(mx1, __shfl_xor_sync(0xffffffffu, mx1, o));
    }
    if (lane == 0) {
        size_t base = (size_t)(a * NB + b) * NHW + p;
        g_avg[base]     = sum0 * (1.0f / (float)NC);
        g_avg[base + 1] = sum1 * (1.0f / (float)NC);
        g_maxm[base]     = mx0;
        g_maxm[base + 1] = mx1;
    }
}

__global__ void k_conv(const float* __restrict__ wsp) {
    __shared__ float sw[98];
    int tid = threadIdx.x;
    if (tid < 98) sw[tid] = wsp[tid];
    __syncthreads();
    int id = blockIdx.x * 256 + tid;
    int ab = id >> 14;
    int p = id & (NHW - 1);
    int py = p >> 7, px = p & 127;
    const float* av = g_avg + (size_t)ab * NHW;
    const float* mxp = g_maxm + (size_t)ab * NHW;
    float acc = 0.f;
#pragma unroll
    for (int ky = 0; ky < 7; ky++) {
        int yy = py + ky - 3;
        if ((unsigned)yy < 128u) {
#pragma unroll
            for (int kx = 0; kx < 7; kx++) {
                int xx = px + kx - 3;
                if ((unsigned)xx < 128u) {
                    int q = yy * NW + xx;
                    acc = fmaf(sw[ky * 7 + kx], av[q], acc);
                    acc = fmaf(sw[49 + ky * 7 + kx], mxp[q], acc);
                }
            }
        }
    }
    g_sa[id] = sigm(acc);
}

// Fused inverse pass, 1 warp / pixel. Axis-aligned angles (|sin|~0 or |cos|~0)
// map the grid onto itself: inverse(forward) composition is an exact identity,
// so the contribution collapses to res += ca * sa[p_inv] * x[q] -- one row
// load and ~35 instructions instead of the 16-cell loop. Diagonal angles keep
// the R6 predicated 16-cell dedup loop (fp32 FFMA accumulation).
__global__ void __launch_bounds__(512, 2) k_fused(float* __restrict__ out) {
    __shared__ float s[16][260];
    int b = blockIdx.x >> 10;            // 1024 16-pixel tiles per image
    int q0 = (blockIdx.x & 1023) * 16;
    int wid = threadIdx.x >> 5, lane = threadIdx.x & 31;
    int q = q0 + wid;
    float X = ncoord(q & 127), Y = ncoord(q >> 7);
    const __half* xb = g_xh + (size_t)b * NHW * NC;
    float res[8];
#pragma unroll
    for (int i = 0; i < 8; i++) res[i] = 0.f;

#pragma unroll
    for (int a = 0; a < NANG; a++) {
        float c_ = g_trig[2 * a], s_ = g_trig[2 * a + 1];
        const float* saab = g_sa + (size_t)(a * NB + b) * NHW;
        const float4* car = (const float4*)(g_ca + (size_t)(a * NB + b) * NC);
        float gx = c_ * X + s_ * Y, gy = -s_ * X + c_ * Y;   // inverse grid
        float ixv = (gx + 1.0f) * 63.5f, iyv = (gy + 1.0f) * 63.5f;

        if (fabsf(s_) < 1e-4f || fabsf(c_) < 1e-4f) {
            // grid-preserving rotation: composition is identity on cells
            int pxi = (int)(ixv + 0.5f), pyi = (int)(iyv + 0.5f);
            float sav = saab[pyi * NW + pxi];
            float t[8];
#pragma unroll
            for (int i = 0; i < 8; i++) t[i] = 0.f;
            const uint4* row = (const uint4*)(xb + ((q >> 7) * NW + (q & 127)) * NC);
            acc_row8(t, sav, row[lane]);
            float4 ca0 = car[lane * 2], ca1 = car[lane * 2 + 1];
            res[0] = fmaf(ca0.x, t[0], res[0]); res[1] = fmaf(ca0.y, t[1], res[1]);
            res[2] = fmaf(ca0.z, t[2], res[2]); res[3] = fmaf(ca0.w, t[3], res[3]);
            res[4] = fmaf(ca1.x, t[4], res[4]); res[5] = fmaf(ca1.y, t[5], res[5]);
            res[6] = fmaf(ca1.z, t[6], res[6]); res[7] = fmaf(ca1.w, t[7], res[7]);
            continue;
        }

        float x0 = floorf(ixv), y0 = floorf(iyv);
        float wx1 = ixv - x0, wx0 = 1.0f - wx1;
        float wy1 = iyv - y0, wy0 = 1.0f - wy1;

        // pass 1: bounding corner of forward-mapped inverse corners
        float minfx = 1e9f, minfy = 1e9f;
#pragma unroll
        for (int j = 0; j < 4; j++) {
            float fpx = x0 + (float)(j & 1);
            float fpy = y0 + (float)(j >> 1);
            float wi = ((j & 1) ? wx1 : wx0) * ((j >> 1) ? wy1 : wy0);
            if (fpx >= 0.f && fpx <= 127.f && fpy >= 0.f && fpy <= 127.f && wi > WEPS) {
                float fgx = c_ * ncoordf(fpx) - s_ * ncoordf(fpy);
                float fgy = s_ * ncoordf(fpx) + c_ * ncoordf(fpy);
                minfx = fminf(minfx, (fgx + 1.0f) * 63.5f);
                minfy = fminf(minfy, (fgy + 1.0f) * 63.5f);
            }
        }
        if (minfx < 500.f) {
            int bx = (int)floorf(minfx), by = (int)floorf(minfy);
            float cellx = (float)(bx + (lane & 3));
            float celly = (float)(by + ((lane >> 2) & 3));
            // pass 2: this lane's cell weight (lanes 0..15 meaningful)
            float wc = 0.f;
#pragma unroll
            for (int j = 0; j < 4; j++) {
                float fpx = x0 + (float)(j & 1);
                float fpy = y0 + (float)(j >> 1);
                float wi = ((j & 1) ? wx1 : wx0) * ((j >> 1) ? wy1 : wy0);
                if (fpx >= 0.f && fpx <= 127.f && fpy >= 0.f && fpy <= 127.f && wi > WEPS) {
                    float sav = saab[(int)fpy * NW + (int)fpx];
                    float fgx = c_ * ncoordf(fpx) - s_ * ncoordf(fpy);
                    float fgy = s_ * ncoordf(fpx) + c_ * ncoordf(fpy);
                    float tx = fmaxf(0.f, 1.0f - fabsf((fgx + 1.0f) * 63.5f - cellx));
                    float ty = fmaxf(0.f, 1.0f - fabsf((fgy + 1.0f) * 63.5f - celly));
                    wc = fmaf(wi * sav, tx * ty, wc);
                }
            }
            float t[8];
#pragma unroll
            for (int i = 0; i < 8; i++) t[i] = 0.f;
#pragma unroll
            for (int k = 0; k < 16; k++) {
                float w = __shfl_sync(0xffffffffu, wc, k);
                int cxk = bx + (k & 3), cyk = by + (k >> 2);
                if (w > WEPS && (unsigned)cxk < 128u && (unsigned)cyk < 128u) {
                    const uint4* row = (const uint4*)(xb + (cyk * NW + cxk) * NC);
                    acc_row8(t, w, row[lane]);
                }
            }
            float4 ca0 = car[lane * 2], ca1 = car[lane * 2 + 1];
            res[0] = fmaf(ca0.x, t[0], res[0]); res[1] = fmaf(ca0.y, t[1], res[1]);
            res[2] = fmaf(ca0.z, t[2], res[2]); res[3] = fmaf(ca0.w, t[3], res[3]);
            res[4] = fmaf(ca1.x, t[4], res[4]); res[5] = fmaf(ca1.y, t[5], res[5]);
            res[6] = fmaf(ca1.z, t[6], res[6]); res[7] = fmaf(ca1.w, t[7], res[7]);
        }
    }

    // smem transpose: s[pixel][channel] -> NCHW stores with /4 folded in
    *(float4*)&s[wid][lane * 8]     = make_float4(res[0], res[1], res[2], res[3]);
    *(float4*)&s[wid][lane * 8 + 4] = make_float4(res[4], res[5], res[6], res[7]);
    __syncthreads();
    int pix = lane & 15, hl = lane >> 4;
#pragma unroll
    for (int it = 0; it < 8; it++) {
        int c = wid * 16 + hl * 8 + it;
        float v = s[pix][c];
        out[((size_t)(b * NC + c)) * NHW + q0 + pix] = v * 0.25f;
    }
}

// ---------------- launch ----------------
extern "C" void kernel_launch(void* const* d_in, const int* in_sizes, int n_in,
                              void* d_out, int out_size) {
    const float* x      = (const float*)d_in[0];
    const float* angles = (const float*)d_in[1];
    const float* w1     = (const float*)d_in[2];
    const float* bng    = (const float*)d_in[3];
    const float* bnb    = (const float*)d_in[4];
    const float* bnm    = (const float*)d_in[5];
    const float* bnv    = (const float*)d_in[6];
    const float* w2     = (const float*)d_in[7];
    const float* wsp    = (const float*)d_in[8];
    float* out = (float*)d_out;

    dim3 tb(32, 32);
    k_Amap<<<(NANG * NHW) / 256, 256>>>(angles);
    k_transpose_mean<<<dim3(NPT, NC / 64, NB), tb>>>(x);
    k_chatt<<<NANG * NB, 256>>>(w1, bng, bnb, bnm, bnv, w2);
    k_avgmax<<<(NANG * NB * NHW / 2) / 8, 256>>>();
    k_conv<<<(NANG * NB * NHW) / 256, 256>>>(wsp);
    k_fused<<<NB * NHW / 16, 512>>>(out);
}

// round 10
// speedup vs baseline: 1.9464x; 1.0579x over previous
#include <cuda_runtime.h>
#include <cuda_fp16.h>
#include <math.h>

#define NB   8
#define NC   256
#define NH   128
#define NW   128
#define NHW  16384
#define NMID 64
#define NANG 4
#define NPT  512
#define WEPS 1e-5f

// ---------------- scratch (static __device__, no allocations) ----------------
__device__ __half g_xh[(size_t)NB * NHW * NC];     // 67 MB  x in NHWC fp16
__device__ float g_trig[2 * NANG];
__device__ float g_A[NANG * NHW];
__device__ float g_mpart[(size_t)NANG * NB * NC * NPT];
__device__ float g_ca[NANG * NB * NC];
__device__ float g_avg[(size_t)NANG * NB * NHW];
__device__ float g_maxm[(size_t)NANG * NB * NHW];
__device__ float g_sa[(size_t)NANG * NB * NHW];
// precomputed geometry (batch-invariant)
__device__ int4   g_gidx[NANG * NHW];              // fwd gather corner pixel idx (-1 = skip)
__device__ float4 g_gw[NANG * NHW];                // fwd gather corner weights
__device__ float4 g_T[(size_t)NANG * NHW * 16];    // fused: per-cell 4-corner tent weights
__device__ int4   g_pinv[NANG * NHW];              // fused: inverse-corner sa indices
__device__ int    g_anchor[NANG * NHW];            // fused: packed (bx+8)|((by+8)<<16)

// ---------------- helpers ----------------
__device__ __forceinline__ float ncoord(int j) { return -1.0f + (float)j * (2.0f / 127.0f); }
__device__ __forceinline__ float ncoordf(float j) { return -1.0f + j * (2.0f / 127.0f); }
__device__ __forceinline__ float sigm(float v) { return 1.0f / (1.0f + expf(-v)); }

// Accumulate w * 8 fp16 channels (one uint4 row chunk) into fp32 acc[8].
__device__ __forceinline__ void acc_row8(float* acc, float w, const uint4 h) {
    const __half2* hp = (const __half2*)&h;
#pragma unroll
    for (int i = 0; i < 4; i++) {
        float2 f = __half22float2(hp[i]);
        acc[2 * i]     = fmaf(w, f.x, acc[2 * i]);
        acc[2 * i + 1] = fmaf(w, f.y, acc[2 * i + 1]);
    }
}

// ---------------- kernels ----------------

// A map + batch-invariant geometry precompute; one thread per (angle, pixel).
__global__ void k_Amap(const float* __restrict__ angles) {
    int id = blockIdx.x * 256 + threadIdx.x;
    int a = id >> 14, p = id & (NHW - 1);
    float ang = angles[a];
    float c_ = cosf(ang), s_ = sinf(ang);
    if (blockIdx.x == 0 && threadIdx.x < NANG) {
        float aa = angles[threadIdx.x];
        g_trig[2 * threadIdx.x]     = cosf(aa);
        g_trig[2 * threadIdx.x + 1] = sinf(aa);
    }
    int sy = p >> 7, sx = p & 127;

    // ---- A map (source-pixel weight accumulation) ----
    {
        float dx = (float)sx - 63.5f, dy = (float)sy - 63.5f;
        float pxf = c_ * dx + s_ * dy + 63.5f;
        float pyf = -s_ * dx + c_ * dy + 63.5f;
        int px0 = (int)floorf(pxf + 0.5f) - 2;
        int py0 = (int)floorf(pyf + 0.5f) - 2;
        float acc = 0.f;
        for (int py = py0; py < py0 + 5; py++) {
            for (int px = px0; px < px0 + 5; px++) {
                if ((unsigned)px < 128u && (unsigned)py < 128u) {
                    float X = ncoord(px), Y = ncoord(py);
                    float gx = c_ * X - s_ * Y, gy = s_ * X + c_ * Y;
                    float ix = (gx + 1.0f) * 63.5f, iy = (gy + 1.0f) * 63.5f;
                    float tx = 1.0f - fabsf(ix - (float)sx);
                    float ty = 1.0f - fabsf(iy - (float)sy);
                    if (tx > 0.f && ty > 0.f) acc += tx * ty;
                }
            }
        }
        g_A[id] = acc * (1.0f / (float)NHW);
    }

    float X = ncoord(sx), Y = ncoord(sy);

    // ---- forward-gather corner geometry (for k_avgmax) ----
    {
        float gx = c_ * X - s_ * Y, gy = s_ * X + c_ * Y;
        float fix = (gx + 1.0f) * 63.5f, fiy = (gy + 1.0f) * 63.5f;
        float fx0 = floorf(fix), fy0 = floorf(fiy);
        float wx1 = fix - fx0, wx0 = 1.0f - wx1;
        float wy1 = fiy - fy0, wy0 = 1.0f - wy1;
        float cx[4] = {fx0, fx0 + 1.0f, fx0,        fx0 + 1.0f};
        float cy[4] = {fy0, fy0,        fy0 + 1.0f, fy0 + 1.0f};
        float cw[4] = {wx0 * wy0, wx1 * wy0, wx0 * wy1, wx1 * wy1};
        int gi[4]; float gw[4];
#pragma unroll
        for (int k = 0; k < 4; k++) {
            bool ok = (cx[k] >= 0.f && cx[k] <= 127.f && cy[k] >= 0.f &&
                       cy[k] <= 127.f && cw[k] > WEPS);
            gi[k] = ok ? ((int)cy[k] * NW + (int)cx[k]) : -1;
            gw[k] = cw[k];
        }
        g_gidx[id] = make_int4(gi[0], gi[1], gi[2], gi[3]);
        g_gw[id]   = make_float4(gw[0], gw[1], gw[2], gw[3]);
    }

    // ---- inverse-pass cell-weight matrix (for k_fused diagonal path) ----
    {
        float gx = c_ * X + s_ * Y, gy = -s_ * X + c_ * Y;   // inverse grid
        float ixv = (gx + 1.0f) * 63.5f, iyv = (gy + 1.0f) * 63.5f;
        float x0 = floorf(ixv), y0 = floorf(iyv);
        float wx1 = ixv - x0, wx0 = 1.0f - wx1;
        float wy1 = iyv - y0, wy0 = 1.0f - wy1;

        float fx[4], fy[4], wj[4];
        int pj[4];
        float minfx = 1e9f, minfy = 1e9f;
#pragma unroll
        for (int j = 0; j < 4; j++) {
            float fpx = x0 + (float)(j & 1);
            float fpy = y0 + (float)(j >> 1);
            float wi = ((j & 1) ? wx1 : wx0) * ((j >> 1) ? wy1 : wy0);
            bool ok = (fpx >= 0.f && fpx <= 127.f && fpy >= 0.f && fpy <= 127.f &&
                       wi > WEPS);
            wj[j] = ok ? wi : 0.f;
            pj[j] = ok ? ((int)fpy * NW + (int)fpx) : 0;
            if (ok) {
                float fgx = c_ * ncoordf(fpx) - s_ * ncoordf(fpy);
                float fgy = s_ * ncoordf(fpx) + c_ * ncoordf(fpy);
                fx[j] = (fgx + 1.0f) * 63.5f;
                fy[j] = (fgy + 1.0f) * 63.5f;
                minfx = fminf(minfx, fx[j]);
                minfy = fminf(minfy, fy[j]);
            } else {
                fx[j] = 1e9f; fy[j] = 1e9f;
            }
        }
        int bx = 0, by = 0;
        if (minfx < 500.f) {
            bx = (int)floorf(minfx);
            by = (int)floorf(minfy);
        }
        g_anchor[id] = (bx + 8) | ((by + 8) << 16);
        g_pinv[id] = make_int4(pj[0], pj[1], pj[2], pj[3]);
        float4* Trow = g_T + (size_t)id * 16;
#pragma unroll
        for (int cell = 0; cell < 16; cell++) {
            float cellx = (float)(bx + (cell & 3));
            float celly = (float)(by + ((cell >> 2) & 3));
            float t[4];
#pragma unroll
            for (int j = 0; j < 4; j++) {
                float tx = fmaxf(0.f, 1.0f - fabsf(fx[j] - cellx));
                float ty = fmaxf(0.f, 1.0f - fabsf(fy[j] - celly));
                t[j] = wj[j] * tx * ty;
            }
            Trow[cell] = make_float4(t[0], t[1], t[2], t[3]);
        }
    }
}

// NCHW -> NHWC(fp16) transpose (64-channel tiles, half2 stores) fused with
// per-angle weighted-mean partials (fp32).
__global__ void k_transpose_mean(const float* __restrict__ x) {
    __shared__ float s[64][33];
    int b = blockIdx.z, c0 = blockIdx.y * 64, p0 = blockIdx.x * 32;
    int tx = threadIdx.x, ty = threadIdx.y;
    float v0 = x[((size_t)(b * NC + c0 + ty)) * NHW + p0 + tx];
    float v1 = x[((size_t)(b * NC + c0 + 32 + ty)) * NHW + p0 + tx];
    s[ty][tx] = v0;
    s[ty + 32][tx] = v1;
#pragma unroll
    for (int a = 0; a < NANG; a++) {
        float Aw = g_A[a * NHW + p0 + tx];
        float r0 = v0 * Aw, r1 = v1 * Aw;
#pragma unroll
        for (int o = 16; o; o >>= 1) {
            r0 += __shfl_xor_sync(0xffffffffu, r0, o);
            r1 += __shfl_xor_sync(0xffffffffu, r1, o);
        }
        if (tx == 0) {
            size_t base = ((size_t)((a * NB + b) * NC + c0 + ty)) * NPT + blockIdx.x;
            g_mpart[base] = r0;
            g_mpart[base + (size_t)32 * NPT] = r1;
        }
    }
    __syncthreads();
    __half2 h2 = __floats2half2_rn(s[2 * tx][ty], s[2 * tx + 1][ty]);
    *(__half2*)(g_xh + ((size_t)b * NHW + p0 + ty) * NC + c0 + 2 * tx) = h2;
}

// Mean reduction (512 partials/channel) + channel attention MLP, one block per (a,b).
__global__ void k_chatt(const float* __restrict__ w1, const float* __restrict__ bng,
                        const float* __restrict__ bnb, const float* __restrict__ bnm,
                        const float* __restrict__ bnv, const float* __restrict__ w2) {
    __shared__ float sm[NC];
    __shared__ float sh[NMID];
    int ab = blockIdx.x;
    int tid = threadIdx.x;
    {
        const float4* src = (const float4*)(g_mpart + (size_t)(ab * NC + tid) * NPT);
        float ssum = 0.f;
#pragma unroll 4
        for (int i = 0; i < NPT / 4; i++) {
            float4 v = src[i];
            ssum += (v.x + v.y) + (v.z + v.w);
        }
        sm[tid] = ssum;
    }
    __syncthreads();
    if (tid < NMID) {
        float hv = 0.f;
        const float* w1r = w1 + tid * NC;
        for (int c = 0; c < NC; c++) hv = fmaf(sm[c], w1r[c], hv);
        hv = (hv - bnm[tid]) * rsqrtf(bnv[tid] + 1e-5f) * bng[tid] + bnb[tid];
        sh[tid] = fmaxf(hv, 0.f);
    }
    __syncthreads();
    float cv = 0.f;
    const float* w2r = w2 + tid * NMID;
    for (int j = 0; j < NMID; j++) cv = fmaf(sh[j], w2r[j], cv);
    g_ca[ab * NC + tid] = sigm(cv);
}

// Channel-attended rotated stats; 2 adjacent pixels per warp.
// Geometry (corner indices + weights) precomputed in k_Amap.
__global__ void k_avgmax() {
    int w2 = blockIdx.x * 8 + (threadIdx.x >> 5);
    int lane = threadIdx.x & 31;
    int a = w2 >> 16;
    int b = (w2 >> 13) & 7;
    int p = (w2 & 8191) * 2;
    const __half* xb = g_xh + (size_t)b * NHW * NC;
    int gid = a * NHW + p;
    int4 gi0 = g_gidx[gid], gi1 = g_gidx[gid + 1];
    float4 gw0 = g_gw[gid], gw1 = g_gw[gid + 1];
    float acc0[8], acc1[8];
#pragma unroll
    for (int i = 0; i < 8; i++) { acc0[i] = 0.f; acc1[i] = 0.f; }
    {
        int gia[4] = {gi0.x, gi0.y, gi0.z, gi0.w};
        float gwa[4] = {gw0.x, gw0.y, gw0.z, gw0.w};
#pragma unroll
        for (int k = 0; k < 4; k++)
            if (gia[k] >= 0)
                acc_row8(acc0, gwa[k], ((const uint4*)(xb + (size_t)gia[k] * NC))[lane]);
    }
    {
        int gia[4] = {gi1.x, gi1.y, gi1.z, gi1.w};
        float gwa[4] = {gw1.x, gw1.y, gw1.z, gw1.w};
#pragma unroll
        for (int k = 0; k < 4; k++)
            if (gia[k] >= 0)
                acc_row8(acc1, gwa[k], ((const uint4*)(xb + (size_t)gia[k] * NC))[lane]);
    }
    const float4* car = (const float4*)(g_ca + (size_t)(a * NB + b) * NC);
    float4 ca0 = car[lane * 2], ca1 = car[lane * 2 + 1];
    float cav[8] = {ca0.x, ca0.y, ca0.z, ca0.w, ca1.x, ca1.y, ca1.z, ca1.w};
    float sum0 = 0.f, mx0 = -1e30f, sum1 = 0.f, mx1 = -1e30f;
#pragma unroll
    for (int i = 0; i < 8; i++) {
        float u = cav[i] * acc0[i], v = cav[i] * acc1[i];
        sum0 += u; mx0 = fmaxf(mx0, u);
        sum1 += v; mx1 = fmaxf(mx1, v);
    }
#pragma unroll
    for (int o = 16; o; o >>= 1) {
        sum0 += __shfl_xor_sync(0xffffffffu, sum0, o);
        mx0 = fmaxf(mx0, __shfl_xor_sync(0xffffffffu, mx0, o));
        sum1 += __shfl_xor_sync(0xffffffffu, sum1, o);
        mx1 = fmaxf(mx1, __shfl_xor_sync(0xffffffffu, mx1, o));
    }
    if (lane == 0) {
        size_t base = (size_t)(a * NB + b) * NHW + p;
        g_avg[base]     = sum0 * (1.0f / (float)NC);
        g_avg[base + 1] = sum1 * (1.0f / (float)NC);
        g_maxm[base]     = mx0;
        g_maxm[base + 1] = mx1;
    }
}

__global__ void k_conv(const float* __restrict__ wsp) {
    __shared__ float sw[98];
    int tid = threadIdx.x;
    if (tid < 98) sw[tid] = wsp[tid];
    __syncthreads();
    int id = blockIdx.x * 256 + tid;
    int ab = id >> 14;
    int p = id & (NHW - 1);
    int py = p >> 7, px = p & 127;
    const float* av = g_avg + (size_t)ab * NHW;
    const float* mxp = g_maxm + (size_t)ab * NHW;
    float acc = 0.f;
#pragma unroll
    for (int ky = 0; ky < 7; ky++) {
        int yy = py + ky - 3;
        if ((unsigned)yy < 128u) {
#pragma unroll
            for (int kx = 0; kx < 7; kx++) {
                int xx = px + kx - 3;
                if ((unsigned)xx < 128u) {
                    int q = yy * NW + xx;
                    acc = fmaf(sw[ky * 7 + kx], av[q], acc);
                    acc = fmaf(sw[49 + ky * 7 + kx], mxp[q], acc);
                }
            }
        }
    }
    g_sa[id] = sigm(acc);
}

// Fused inverse pass, 1 warp / pixel. Axis-aligned angles use the exact
// identity shortcut; diagonal angles use PRECOMPUTED cell-weight matrices:
// wc(cell) = dot(T[a,q,cell], sa[corners]) -- no geometry recompute.
__global__ void __launch_bounds__(512, 2) k_fused(float* __restrict__ out) {
    __shared__ float s[16][260];
    int b = blockIdx.x >> 10;            // 1024 16-pixel tiles per image
    int q0 = (blockIdx.x & 1023) * 16;
    int wid = threadIdx.x >> 5, lane = threadIdx.x & 31;
    int q = q0 + wid;
    float X = ncoord(q & 127), Y = ncoord(q >> 7);
    const __half* xb = g_xh + (size_t)b * NHW * NC;
    float res[8];
#pragma unroll
    for (int i = 0; i < 8; i++) res[i] = 0.f;

#pragma unroll
    for (int a = 0; a < NANG; a++) {
        float c_ = g_trig[2 * a], s_ = g_trig[2 * a + 1];
        const float* saab = g_sa + (size_t)(a * NB + b) * NHW;
        const float4* car = (const float4*)(g_ca + (size_t)(a * NB + b) * NC);

        float t[8];
#pragma unroll
        for (int i = 0; i < 8; i++) t[i] = 0.f;

        if (fabsf(s_) < 1e-4f || fabsf(c_) < 1e-4f) {
            // grid-preserving rotation: composition is identity on cells
            float gx = c_ * X + s_ * Y, gy = -s_ * X + c_ * Y;
            int pxi = (int)((gx + 1.0f) * 63.5f + 0.5f);
            int pyi = (int)((gy + 1.0f) * 63.5f + 0.5f);
            float sav = saab[pyi * NW + pxi];
            const uint4* row = (const uint4*)(xb + ((q >> 7) * NW + (q & 127)) * NC);
            acc_row8(t, sav, row[lane]);
        } else {
            int gid = a * NHW + q;
            int anch = g_anchor[gid];
            int bx = (anch & 0xffff) - 8, by = (anch >> 16) - 8;
            int4 pj = g_pinv[gid];
            float sa0 = saab[pj.x], sa1 = saab[pj.y];
            float sa2 = saab[pj.z], sa3 = saab[pj.w];
            float4 T = g_T[(size_t)gid * 16 + (lane & 15)];
            float wc = T.x * sa0 + T.y * sa1 + T.z * sa2 + T.w * sa3;
#pragma unroll
            for (int k = 0; k < 16; k++) {
                float w = __shfl_sync(0xffffffffu, wc, k);
                int cxk = bx + (k & 3), cyk = by + (k >> 2);
                if (w > WEPS && (unsigned)cxk < 128u && (unsigned)cyk < 128u) {
                    const uint4* row = (const uint4*)(xb + (cyk * NW + cxk) * NC);
                    acc_row8(t, w, row[lane]);
                }
            }
        }

        float4 ca0 = car[lane * 2], ca1 = car[lane * 2 + 1];
        res[0] = fmaf(ca0.x, t[0], res[0]); res[1] = fmaf(ca0.y, t[1], res[1]);
        res[2] = fmaf(ca0.z, t[2], res[2]); res[3] = fmaf(ca0.w, t[3], res[3]);
        res[4] = fmaf(ca1.x, t[4], res[4]); res[5] = fmaf(ca1.y, t[5], res[5]);
        res[6] = fmaf(ca1.z, t[6], res[6]); res[7] = fmaf(ca1.w, t[7], res[7]);
    }

    // smem transpose: s[pixel][channel] -> NCHW stores with /4 folded in
    *(float4*)&s[wid][lane * 8]     = make_float4(res[0], res[1], res[2], res[3]);
    *(float4*)&s[wid][lane * 8 + 4] = make_float4(res[4], res[5], res[6], res[7]);
    __syncthreads();
    int pix = lane & 15, hl = lane >> 4;
#pragma unroll
    for (int it = 0; it < 8; it++) {
        int c = wid * 16 + hl * 8 + it;
        float v = s[pix][c];
        out[((size_t)(b * NC + c)) * NHW + q0 + pix] = v * 0.25f;
    }
}

// ---------------- launch ----------------
extern "C" void kernel_launch(void* const* d_in, const int* in_sizes, int n_in,
                              void* d_out, int out_size) {
    const float* x      = (const float*)d_in[0];
    const float* angles = (const float*)d_in[1];
    const float* w1     = (const float*)d_in[2];
    const float* bng    = (const float*)d_in[3];
    const float* bnb    = (const float*)d_in[4];
    const float* bnm    = (const float*)d_in[5];
    const float* bnv    = (const float*)d_in[6];
    const float* w2     = (const float*)d_in[7];
    const float* wsp    = (const float*)d_in[8];
    float* out = (float*)d_out;

    dim3 tb(32, 32);
    k_Amap<<<(NANG * NHW) / 256, 256>>>(angles);
    k_transpose_mean<<<dim3(NPT, NC / 64, NB), tb>>>(x);
    k_chatt<<<NANG * NB, 256>>>(w1, bng, bnb, bnm, bnv, w2);
    k_avgmax<<<(NANG * NB * NHW / 2) / 8, 256>>>();
    k_conv<<<(NANG * NB * NHW) / 256, 256>>>(wsp);
    k_fused<<<NB * NHW / 16, 512>>>(out);
}